// round 15
// baseline (speedup 1.0000x reference)
#include <cuda_runtime.h>
#include <stdint.h>

#define HH 256
#define WW 256
#define NPIX (HH*WW)
#define TW 32
#define TH 16
#define NBLK 128u

// ---------------- scratch (device globals; no allocations allowed) -------------
__device__ float g_flow1[2*NPIX];   // vector + subpixel (before median)
__device__ unsigned int g_bar;      // grid barrier counter (monotonic across replays)

// packed rank table: (spiral_rank(s) << 6) | s   for s = (dj+3)*7 + (di+3)
__constant__ int c_rank[49] = {
    (42<<6)|0,(43<<6)|1,(44<<6)|2,(45<<6)|3,(46<<6)|4,(47<<6)|5,(48<<6)|6,
    (41<<6)|7,(20<<6)|8,(21<<6)|9,(22<<6)|10,(23<<6)|11,(24<<6)|12,(25<<6)|13,
    (40<<6)|14,(19<<6)|15,(6<<6)|16,(7<<6)|17,(8<<6)|18,(9<<6)|19,(26<<6)|20,
    (39<<6)|21,(18<<6)|22,(5<<6)|23,(0<<6)|24,(1<<6)|25,(10<<6)|26,(27<<6)|27,
    (38<<6)|28,(17<<6)|29,(4<<6)|30,(3<<6)|31,(2<<6)|32,(11<<6)|33,(28<<6)|34,
    (37<<6)|35,(16<<6)|36,(15<<6)|37,(14<<6)|38,(13<<6)|39,(12<<6)|40,(29<<6)|41,
    (36<<6)|42,(35<<6)|43,(34<<6)|44,(33<<6)|45,(32<<6)|46,(31<<6)|47,(30<<6)|48
};

#define BAR(id, cnt) asm volatile("bar.sync %0, %1;" :: "r"(id), "r"(cnt) : "memory")

__device__ __forceinline__ float imload(const float* __restrict__ img, int y, int x) {
    y = min(max(y, 0), HH - 1);
    x = min(max(x, 0), WW - 1);
    return __ldg(&img[y * WW + x]);
}

__device__ __forceinline__ unsigned char quant(float v) {
    float r = rintf(v * 255.0f);          // round half-to-even, matches jnp.round
    r = fminf(fmaxf(r, 0.0f), 255.0f);
    return (unsigned char)r;
}

__device__ __forceinline__ void mnmx(float& a, float& b) {
    float t = fminf(a, b);
    b = fmaxf(a, b);
    a = t;
}
__device__ __forceinline__ float median9(float p0, float p1, float p2,
                                         float p3, float p4, float p5,
                                         float p6, float p7, float p8) {
    mnmx(p1, p2); mnmx(p4, p5); mnmx(p7, p8);
    mnmx(p0, p1); mnmx(p3, p4); mnmx(p6, p7);
    mnmx(p1, p2); mnmx(p4, p5); mnmx(p7, p8);
    mnmx(p0, p3); mnmx(p5, p8); mnmx(p4, p7);
    mnmx(p3, p6); mnmx(p1, p4); mnmx(p2, p5);
    mnmx(p4, p7); mnmx(p4, p2); mnmx(p6, p4);
    mnmx(p4, p2);
    return p4;
}

// phase-overlaid shared memory (sfb + merge arrays persist outside the union)
struct SmemA {
    alignas(16) float rawf[28][48];           // origin (by-6, bx-8)
    alignas(16) float vertf[26][48];          // rows (by-5), cols (bx-8)
    alignas(16) unsigned char sfq[26][56];    // origin (by-5, bx-5); cols 0..41 data, 42..47 zero
    alignas(16) uint32_t sfqs[4][26][12];     // shifted copies; plane stride 312 (mod32=24)
    alignas(16) uint32_t sfqsH[4][26][12];    // pre-masked hi bytes (same bank layout)
    alignas(16) float rawg[22][40];           // origin (by-3, bx-4)
    alignas(16) float vertg[20][40];          // rows (by-2), cols (bx-4)
    alignas(16) unsigned char sgq[20][40];    // origin (by-2, bx-2); cols 36..39 zero
    float sdx[20][36];                        // origin (by-2, bx-2)
    float sdy[20][36];
};
struct SmemB {
    float sflow[2][22][38];   // flow, halo 3, replicate clamp; origin (by-3, bx-3)
    float smed[2][20][36];    // median flow, halo 2, zero outside; origin (by-2, bx-2)
    float sguide[20][36];     // fb guide, halo 2, zero outside
};

// =====================================================================
// One fused kernel, 128 blocks x 1024 threads (32x16 tile).
// R14 structure + interior-block specialization of phase B.
// =====================================================================
__global__ __launch_bounds__(1024, 1) void flow_fused(const float* __restrict__ f,
                                                      const float* __restrict__ g,
                                                      float* __restrict__ out) {
    __shared__ float sfb[26][42];             // origin (by-5, bx-5); persists to phase B
    __shared__ int   sbest[2][16][32];
    __shared__ float sacc[5][16][32];         // LK partials / bilateral partials
    __shared__ __align__(16) unsigned char smem_raw[
        sizeof(SmemA) > sizeof(SmemB) ? sizeof(SmemA) : sizeof(SmemB)];
    SmemA& A = *reinterpret_cast<SmemA*>(smem_raw);
    SmemB& B = *reinterpret_cast<SmemB*>(smem_raw);

    const int bx = blockIdx.x * TW, by = blockIdx.y * TH;
    const int tid = threadIdx.x;
    const int w   = tid >> 5;
    const int z   = w & 1;            // warp-uniform work-split id
    const int ty  = w >> 1;           // pixel row 0..15
    const int tx  = tid & 31;         // pixel col 0..31
    const int qb  = 1 + (w >> 2);     // warp-quad barrier id (1..8), 128 threads
    const bool fgrp = (w < 20);       // prep pipeline split
    const int ft = tid;               // 0..639 in f-group
    const int gt = tid - 640;         // 0..383 in g-group
    const bool interior = (blockIdx.x > 0 && blockIdx.x < 7 &&
                           blockIdx.y > 0 && blockIdx.y < 15);

    // ====== PHASE A prep: f-pipeline and g-pipeline fully decoupled ======
    if (fgrp) {
        if (interior) {
            if (ft < 28 * 12) {
                int r = ft / 12, w2 = ft % 12;
                float4 v = __ldg((const float4*)(f + (by - 6 + r) * WW + (bx - 8)) + w2);
                *(float4*)&A.rawf[r][w2 * 4] = v;
            }
        } else {
            for (int i = ft; i < 28 * 48; i += 640) {
                int r = i / 48, c = i % 48;
                A.rawf[r][c] = imload(f, by - 6 + r, bx - 8 + c);
            }
        }
        BAR(9, 640);
        for (int i = ft; i < 26 * 48; i += 640) {
            int r = i / 48, c = i % 48;
            A.vertf[r][c] = (A.rawf[r][c] + 2.0f * A.rawf[r + 1][c] + A.rawf[r + 2][c]) * 0.25f;
        }
        BAR(9, 640);
        for (int i = ft; i < 26 * 48; i += 640) {
            int r = i / 48, c = i % 48;
            unsigned char v = 0;
            if (c < 42) {
                float fb = (A.vertf[r][c + 2] + 2.0f * A.vertf[r][c + 3] + A.vertf[r][c + 4]) * 0.25f;
                sfb[r][c] = fb;
                int y = by - 5 + r, x = bx - 5 + c;
                bool in = (y >= 0 && y < HH && x >= 0 && x < WW);
                v = in ? quant(fb) : (unsigned char)0;
            }
            A.sfq[r][c] = v;
        }
    } else {
        if (interior) {
            if (gt < 22 * 10) {
                int r = gt / 10, w2 = gt % 10;
                float4 v = __ldg((const float4*)(g + (by - 3 + r) * WW + (bx - 4)) + w2);
                *(float4*)&A.rawg[r][w2 * 4] = v;
            }
        } else {
            for (int i = gt; i < 22 * 40; i += 384) {
                int r = i / 40, c = i % 40;
                A.rawg[r][c] = imload(g, by - 3 + r, bx - 4 + c);
            }
        }
        BAR(10, 384);
        for (int i = gt; i < 20 * 40; i += 384) {
            int r = i / 40, c = i % 40;
            A.vertg[r][c] = (A.rawg[r][c] + 2.0f * A.rawg[r + 1][c] + A.rawg[r + 2][c]) * 0.25f;
        }
        BAR(10, 384);
        for (int i = gt; i < 20 * 40; i += 384) {
            int r = i / 40, c = i % 40;
            unsigned char v = 0;
            if (c < 36) {
                float gb = (A.vertg[r][c + 1] + 2.0f * A.vertg[r][c + 2] + A.vertg[r][c + 3]) * 0.25f;
                int y = by - 2 + r, x = bx - 2 + c;
                bool in = (y >= 0 && y < HH && x >= 0 && x < WW);
                v = in ? quant(gb) : (unsigned char)0;
            }
            A.sgq[r][c] = v;
        }
    }
    __syncthreads();   // sfb / sfq / sgq all ready

    // g template: 5 rows (4 bytes + 1 byte) at origin col tx in sgq
    unsigned int glo[5], ghib[5];
    {
        int k2 = tx & 3, w2 = tx >> 2;
        unsigned int sel = 0x3210u + (unsigned)k2 * 0x1111u;
        #pragma unroll
        for (int ky = 0; ky < 5; ky++) {
            const uint32_t* row = (const uint32_t*)A.sgq[ty + ky];
            uint32_t a = row[w2], b2 = row[w2 + 1];
            glo[ky]  = __byte_perm(a, b2, sel);
            ghib[ky] = (b2 >> (8 * k2)) & 0xFFu;
        }
    }

    if (fgrp) {
        for (int i = ft; i < 26 * 44; i += 640) {   // 26 rows x 4 shifts x 11 words
            int r = i / 44, rem = i % 44;
            int k = rem / 11, ww = rem % 11;
            const uint32_t* W = (const uint32_t*)A.sfq[r];
            uint32_t w0 = W[ww], w1 = W[ww + 1];
            A.sfqs[k][r][ww]  = __byte_perm(w0, w1, 0x3210u + (unsigned)k * 0x1111u);
            A.sfqsH[k][r][ww] = (w1 >> (8 * k)) & 0xFFu;
        }
    } else {
        for (int i = gt; i < 20 * 36; i += 384) {   // gradient of fb
            int r = i / 36, c = i % 36;
            int y = by - 2 + r, x = bx - 2 + c;
            bool in = (y >= 0 && y < HH && x >= 0 && x < WW);
            float dyv = 0.0f, dxv = 0.0f;
            if (in) {
                int yn = min(y + 1, HH - 1) - (by - 5);
                int yp = max(y - 1, 0) - (by - 5);
                int xn = min(x + 1, WW - 1) - (bx - 5);
                int xp = max(x - 1, 0) - (bx - 5);
                dyv = (sfb[yn][c + 3] - sfb[yp][c + 3]) * 0.5f;
                dxv = (sfb[r + 3][xn] - sfb[r + 3][xp]) * 0.5f;
            }
            A.sdy[r][c] = dyv;
            A.sdx[r][c] = dxv;
        }
    }
    __syncthreads();   // sfqs + gradients ready

    // SAD: z0 -> dips 0..2 (z0 also merges+solves LK), z1 -> dips 3..6.
    // Two-wave djp per dip to keep register lives short.
    int best = 0x7fffffff;
    const int dipA = z ? 3 : 0;
    const int dipB = z ? 7 : 3;
    #pragma unroll 1
    for (int dip = dipA; dip < dipB; ++dip) {
        int s = tx + dip;                 // 0..37
        int k = s & 3, wi = s >> 2;
        const uint32_t* bp = &A.sfqs[k][ty][wi];
        const uint32_t* hp = &A.sfqsH[k][ty][wi];

        // wave 1: rows 0..7, djp 0..3
        uint32_t flo[8], fhi[8];
        #pragma unroll
        for (int r = 0; r < 8; r++) {
            flo[r] = bp[r * 12];
            fhi[r] = hp[r * 12];
        }
        #pragma unroll
        for (int djp = 0; djp < 4; djp++) {
            unsigned int sad = 0;
            #pragma unroll
            for (int ky = 0; ky < 5; ky++) {
                sad = __dp4a(__vabsdiffu4(flo[djp + ky], glo[ky]), 0x01010101u, sad);
                sad = __usad(fhi[djp + ky], ghib[ky], sad);
            }
            best = min(best, (int)sad * 4096 + c_rank[djp * 7 + dip]);
        }
        // wave 2: rows 8..10, djp 4..6 (rows 4..7 still live)
        uint32_t flo2[3], fhi2[3];
        #pragma unroll
        for (int r = 0; r < 3; r++) {
            flo2[r] = bp[(8 + r) * 12];
            fhi2[r] = hp[(8 + r) * 12];
        }
        #define ROWL(j) ((j) < 8 ? flo[(j)] : flo2[(j) - 8])
        #define ROWH(j) ((j) < 8 ? fhi[(j)] : fhi2[(j) - 8])
        #pragma unroll
        for (int djp = 4; djp < 7; djp++) {
            unsigned int sad = 0;
            #pragma unroll
            for (int ky = 0; ky < 5; ky++) {
                sad = __dp4a(__vabsdiffu4(ROWL(djp + ky), glo[ky]), 0x01010101u, sad);
                sad = __usad(ROWH(djp + ky), ghib[ky], sad);
            }
            best = min(best, (int)sad * 4096 + c_rank[djp * 7 + dip]);
        }
        #undef ROWL
        #undef ROWH
    }
    sbest[z][ty][tx] = best;
    BAR(qb, 128);                          // pair-local exchange via quad barrier
    best = min(best, sbest[z ^ 1][ty][tx]);

    int bestS = best & 63;
    int bjp = bestS / 7, bip = bestS % 7;

    // Lucas-Kanade ring: z0 -> row 0 (5 pts) + merge + solve; z1 -> rows 1..4 (11 pts)
    float sv, su;   // live across the grid barrier on z0 threads
    {
        float a = 0.f, b = 0.f, d = 0.f, pp = 0.f, q = 0.f;
        #define LKP(ky, kx) { \
            float dx = A.sdx[ty + (ky)][tx + (kx)]; \
            float dy = A.sdy[ty + (ky)][tx + (kx)]; \
            float fv = (float)A.sfq[ty + bjp + (ky)][tx + bip + (kx)] * (1.0f / 255.0f); \
            unsigned int gb = ((kx) < 4) ? ((glo[(ky)] >> (8 * (kx))) & 0xFFu) : ghib[(ky)]; \
            float gv = (float)gb * (1.0f / 255.0f); \
            float zd = gv - fv; \
            a += dx * dx; b += dx * dy; d += dy * dy; \
            pp += zd * dx; q += zd * dy; }
        if (z == 0) {
            LKP(0, 0); LKP(0, 1); LKP(0, 2); LKP(0, 3); LKP(0, 4);
        } else {
            LKP(1, 0); LKP(1, 4);
            LKP(2, 0); LKP(2, 4);
            LKP(3, 0); LKP(3, 4);
            LKP(4, 0); LKP(4, 1); LKP(4, 2); LKP(4, 3); LKP(4, 4);
            sacc[0][ty][tx] = a;  sacc[1][ty][tx] = b;  sacc[2][ty][tx] = d;
            sacc[3][ty][tx] = pp; sacc[4][ty][tx] = q;
        }
        #undef LKP
        BAR(qb, 128);                      // pair-local merge via quad barrier
        if (z == 0) {
            a  += sacc[0][ty][tx]; b += sacc[1][ty][tx]; d += sacc[2][ty][tx];
            pp += sacc[3][ty][tx]; q += sacc[4][ty][tx];
            // avoid FMA contraction: thresholds must match the reference rounding
            float det = __fsub_rn(__fmul_rn(a, d), __fmul_rn(b, b));
            float u   = __fsub_rn(__fmul_rn(d, pp), __fmul_rn(b, q));
            float v   = __fsub_rn(__fmul_rn(a, q), __fmul_rn(b, pp));
            bool bad = (det <= 1e-7f);
            float dd = bad ? 1.0f : det;
            sv = v / dd;   // y component
            su = u / dd;   // x component
            if (bad || fabsf(sv) >= 1.0f) sv = 0.0f;
            if (bad || fabsf(su) >= 1.0f) su = 0.0f;
            sv += (float)(3 - bjp);   // -dj + subpixel
            su += (float)(3 - bip);   // -di + subpixel
            int y = by + ty, x = bx + tx;
            g_flow1[y * WW + x]        = sv;
            g_flow1[NPIX + y * WW + x] = su;
        }
    }

    __syncthreads();   // ALL phase-A smem reads complete -> smem reusable
    if (z == 0) {      // stage own interior directly into phase-B smem
        B.sflow[0][ty + 3][tx + 3] = sv;
        B.sflow[1][ty + 3][tx + 3] = su;
    }

    // ====== GRID BARRIER (128 blocks, all co-resident) ======
    __syncthreads();
    if (tid == 0) {
        unsigned int my;
        asm volatile("atom.add.release.gpu.global.u32 %0, [%1], 1;"
                     : "=r"(my) : "l"(&g_bar) : "memory");
        unsigned int target = my - (my & (NBLK - 1u)) + NBLK;   // end of this round
        unsigned int cur;
        do {
            asm volatile("ld.global.acquire.gpu.u32 %0, [%1];"
                         : "=r"(cur) : "l"(&g_bar) : "memory");
            if (cur >= target) break;
            __nanosleep(64);
        } while (true);
    }
    __syncthreads();

    // ====== PHASE B: median + bilateral ======
    // load ONLY the halo ring (22x38 minus the staged 16x32 interior)
    if (tid < 648) {
        int ch = tid >= 324;
        int i = tid - ch * 324;
        int r, c;
        if (i < 114)      { r = i / 38;              c = i % 38; }
        else if (i < 228) { int j = i - 114; r = 19 + j / 38; c = j % 38; }
        else if (i < 276) { int j = i - 228; r = 3 + j / 3;   c = j % 3; }
        else              { int j = i - 276; r = 3 + j / 3;   c = 35 + j % 3; }
        int y = min(max(by - 3 + r, 0), HH - 1);
        int x = min(max(bx - 3 + c, 0), WW - 1);
        B.sflow[ch][r][c] = g_flow1[ch * NPIX + y * WW + x];
    }
    __syncthreads();

    // median: sflow is loaded at CLAMPED coords, so direct indexing == replicate pad
    if (interior) {
        // no image boundary in this tile: no 'in' predicates, unconditional guide
        for (int i = tid; i < 2 * 720; i += 1024) {      // 20 x 36 per channel
            int ch = i >= 720;
            int rem = i - ch * 720;
            int r = rem / 36, c = rem % 36;
            const float (*fl)[38] = B.sflow[ch];
            float m = median9(fl[r][c],     fl[r][c + 1],     fl[r][c + 2],
                              fl[r + 1][c], fl[r + 1][c + 1], fl[r + 1][c + 2],
                              fl[r + 2][c], fl[r + 2][c + 1], fl[r + 2][c + 2]);
            B.smed[ch][r][c] = m;
            if (ch == 0) B.sguide[r][c] = sfb[r + 3][c + 3];
        }
    } else {
        for (int i = tid; i < 2 * 720; i += 1024) {
            int ch = i >= 720;
            int rem = i - ch * 720;
            int r = rem / 36, c = rem % 36;
            int y = by - 2 + r, x = bx - 2 + c;
            bool in = (y >= 0 && y < HH && x >= 0 && x < WW);
            float m = 0.0f;
            if (in) {
                const float (*fl)[38] = B.sflow[ch];
                m = median9(fl[r][c],     fl[r][c + 1],     fl[r][c + 2],
                            fl[r + 1][c], fl[r + 1][c + 1], fl[r + 1][c + 2],
                            fl[r + 2][c], fl[r + 2][c + 1], fl[r + 2][c + 2]);
            }
            B.smed[ch][r][c] = m;
            if (ch == 0) B.sguide[r][c] = in ? sfb[r + 3][c + 3] : 0.0f;
        }
    }
    __syncthreads();

    // bilateral: z0 -> 11 taps + merge + divides; z1 -> 14 taps
    {
        const float KVAL = -1.0f / 4.5f;   // -1/(2*1.5^2)
        const float SII  = 200.0f;         //  1/(2*0.05^2)
        float c = B.sguide[ty + 2][tx + 2];
        float wsum = 0.f, s0 = 0.f, s1 = 0.f;

        #define BTAP(dy, dx) { \
            float tn = B.sguide[ty + (dy)][tx + (dx)]; \
            float df = c - tn; \
            float co = 1.0f - fabsf(KVAL - df * df * SII); \
            co = fminf(fmaxf(co, 0.0f), 1.0f); \
            wsum += co; \
            s0 += B.smed[0][ty + (dy)][tx + (dx)] * co; \
            s1 += B.smed[1][ty + (dy)][tx + (dx)] * co; }

        if (z == 0) {
            #pragma unroll
            for (int dy = 0; dy < 2; dy++)
                #pragma unroll
                for (int dx = 0; dx < 5; dx++) BTAP(dy, dx);
            BTAP(2, 0);
        } else {
            BTAP(2, 1); BTAP(2, 2); BTAP(2, 3); BTAP(2, 4);
            #pragma unroll
            for (int dy = 3; dy < 5; dy++)
                #pragma unroll
                for (int dx = 0; dx < 5; dx++) BTAP(dy, dx);
            sacc[0][ty][tx] = wsum;
            sacc[1][ty][tx] = s0;
            sacc[2][ty][tx] = s1;
        }
        #undef BTAP
        BAR(qb, 128);                      // pair-local merge via quad barrier
        if (z == 0) {
            wsum += sacc[0][ty][tx];
            s0   += sacc[1][ty][tx];
            s1   += sacc[2][ty][tx];
            int y = by + ty, x = bx + tx;
            out[y * WW + x]        = s0 / wsum;
            out[NPIX + y * WW + x] = s1 / wsum;
        }
    }
}

// ---------------- launch ----------------
extern "C" void kernel_launch(void* const* d_in, const int* in_sizes, int n_in,
                              void* d_out, int out_size) {
    const float* f = (const float*)d_in[0];
    const float* g = (const float*)d_in[1];
    float* out = (float*)d_out;

    dim3 grd(WW / TW, HH / TH);   // 8 x 16 = 128 blocks, one per SM
    flow_fused<<<grd, 1024>>>(f, g, out);
}

// round 16
// speedup vs baseline: 1.0172x; 1.0172x over previous
#include <cuda_runtime.h>
#include <stdint.h>

#define HH 256
#define WW 256
#define NPIX (HH*WW)
#define TW 32
#define TH 16
#define NBLK 128u

// ---------------- scratch (device globals; no allocations allowed) -------------
__device__ float g_flow1[2*NPIX];   // vector + subpixel (before median)
__device__ unsigned int g_bar;      // grid barrier counter (monotonic across replays)

// packed rank table: (spiral_rank(s) << 6) | s   for s = (dj+3)*7 + (di+3)
__constant__ int c_rank[49] = {
    (42<<6)|0,(43<<6)|1,(44<<6)|2,(45<<6)|3,(46<<6)|4,(47<<6)|5,(48<<6)|6,
    (41<<6)|7,(20<<6)|8,(21<<6)|9,(22<<6)|10,(23<<6)|11,(24<<6)|12,(25<<6)|13,
    (40<<6)|14,(19<<6)|15,(6<<6)|16,(7<<6)|17,(8<<6)|18,(9<<6)|19,(26<<6)|20,
    (39<<6)|21,(18<<6)|22,(5<<6)|23,(0<<6)|24,(1<<6)|25,(10<<6)|26,(27<<6)|27,
    (38<<6)|28,(17<<6)|29,(4<<6)|30,(3<<6)|31,(2<<6)|32,(11<<6)|33,(28<<6)|34,
    (37<<6)|35,(16<<6)|36,(15<<6)|37,(14<<6)|38,(13<<6)|39,(12<<6)|40,(29<<6)|41,
    (36<<6)|42,(35<<6)|43,(34<<6)|44,(33<<6)|45,(32<<6)|46,(31<<6)|47,(30<<6)|48
};

#define BAR(id, cnt) asm volatile("bar.sync %0, %1;" :: "r"(id), "r"(cnt) : "memory")

__device__ __forceinline__ float imload(const float* __restrict__ img, int y, int x) {
    y = min(max(y, 0), HH - 1);
    x = min(max(x, 0), WW - 1);
    return __ldg(&img[y * WW + x]);
}

__device__ __forceinline__ unsigned char quant(float v) {
    float r = rintf(v * 255.0f);          // round half-to-even, matches jnp.round
    r = fminf(fmaxf(r, 0.0f), 255.0f);
    return (unsigned char)r;
}

__device__ __forceinline__ void mnmx(float& a, float& b) {
    float t = fminf(a, b);
    b = fmaxf(a, b);
    a = t;
}
__device__ __forceinline__ float median9(float p0, float p1, float p2,
                                         float p3, float p4, float p5,
                                         float p6, float p7, float p8) {
    mnmx(p1, p2); mnmx(p4, p5); mnmx(p7, p8);
    mnmx(p0, p1); mnmx(p3, p4); mnmx(p6, p7);
    mnmx(p1, p2); mnmx(p4, p5); mnmx(p7, p8);
    mnmx(p0, p3); mnmx(p5, p8); mnmx(p4, p7);
    mnmx(p3, p6); mnmx(p1, p4); mnmx(p2, p5);
    mnmx(p4, p7); mnmx(p4, p2); mnmx(p6, p4);
    mnmx(p4, p2);
    return p4;
}

// phase-overlaid shared memory (sfb + merge arrays persist outside the union)
struct SmemA {
    alignas(16) float rawf[28][48];           // origin (by-6, bx-8)
    alignas(16) float vertf[26][48];          // rows (by-5), cols (bx-8)
    alignas(16) unsigned char sfq[26][56];    // origin (by-5, bx-5); cols 0..41 data, 42..47 zero
    alignas(16) uint32_t sfqs[4][26][12];     // shifted copies; plane stride 312 (mod32=24)
    alignas(16) uint32_t sfqsH[4][26][12];    // pre-masked hi bytes (same bank layout)
    alignas(16) float rawg[22][40];           // origin (by-3, bx-4)
    alignas(16) float vertg[20][40];          // rows (by-2), cols (bx-4)
    alignas(16) unsigned char sgq[20][40];    // origin (by-2, bx-2); cols 36..39 zero
    float sdx[20][36];                        // origin (by-2, bx-2)
    float sdy[20][36];
};
struct SmemB {
    float sflow[2][22][38];   // flow, halo 3, replicate clamp; origin (by-3, bx-3)
    float smed[2][20][36];    // median flow, halo 2, zero outside; origin (by-2, bx-2)
    float sguide[20][36];     // fb guide, halo 2, zero outside
};

// =====================================================================
// One fused kernel, 128 blocks x 1024 threads (32x16 tile).
// Best measured variant (R14): two-wave djp SAD (short register lives),
// pre-masked hi-byte plane, IMAD score packing, vectorized interior
// loads, clamp-free median, software grid barrier.
// =====================================================================
__global__ __launch_bounds__(1024, 1) void flow_fused(const float* __restrict__ f,
                                                      const float* __restrict__ g,
                                                      float* __restrict__ out) {
    __shared__ float sfb[26][42];             // origin (by-5, bx-5); persists to phase B
    __shared__ int   sbest[2][16][32];
    __shared__ float sacc[5][16][32];         // LK partials / bilateral partials
    __shared__ __align__(16) unsigned char smem_raw[
        sizeof(SmemA) > sizeof(SmemB) ? sizeof(SmemA) : sizeof(SmemB)];
    SmemA& A = *reinterpret_cast<SmemA*>(smem_raw);
    SmemB& B = *reinterpret_cast<SmemB*>(smem_raw);

    const int bx = blockIdx.x * TW, by = blockIdx.y * TH;
    const int tid = threadIdx.x;
    const int w   = tid >> 5;
    const int z   = w & 1;            // warp-uniform work-split id
    const int ty  = w >> 1;           // pixel row 0..15
    const int tx  = tid & 31;         // pixel col 0..31
    const int qb  = 1 + (w >> 2);     // warp-quad barrier id (1..8), 128 threads
    const bool fgrp = (w < 20);       // prep pipeline split
    const int ft = tid;               // 0..639 in f-group
    const int gt = tid - 640;         // 0..383 in g-group
    const bool interior = (blockIdx.x > 0 && blockIdx.x < 7 &&
                           blockIdx.y > 0 && blockIdx.y < 15);

    // ====== PHASE A prep: f-pipeline and g-pipeline fully decoupled ======
    if (fgrp) {
        if (interior) {
            if (ft < 28 * 12) {
                int r = ft / 12, w2 = ft % 12;
                float4 v = __ldg((const float4*)(f + (by - 6 + r) * WW + (bx - 8)) + w2);
                *(float4*)&A.rawf[r][w2 * 4] = v;
            }
        } else {
            for (int i = ft; i < 28 * 48; i += 640) {
                int r = i / 48, c = i % 48;
                A.rawf[r][c] = imload(f, by - 6 + r, bx - 8 + c);
            }
        }
        BAR(9, 640);
        for (int i = ft; i < 26 * 48; i += 640) {
            int r = i / 48, c = i % 48;
            A.vertf[r][c] = (A.rawf[r][c] + 2.0f * A.rawf[r + 1][c] + A.rawf[r + 2][c]) * 0.25f;
        }
        BAR(9, 640);
        for (int i = ft; i < 26 * 48; i += 640) {
            int r = i / 48, c = i % 48;
            unsigned char v = 0;
            if (c < 42) {
                float fb = (A.vertf[r][c + 2] + 2.0f * A.vertf[r][c + 3] + A.vertf[r][c + 4]) * 0.25f;
                sfb[r][c] = fb;
                int y = by - 5 + r, x = bx - 5 + c;
                bool in = (y >= 0 && y < HH && x >= 0 && x < WW);
                v = in ? quant(fb) : (unsigned char)0;
            }
            A.sfq[r][c] = v;
        }
    } else {
        if (interior) {
            if (gt < 22 * 10) {
                int r = gt / 10, w2 = gt % 10;
                float4 v = __ldg((const float4*)(g + (by - 3 + r) * WW + (bx - 4)) + w2);
                *(float4*)&A.rawg[r][w2 * 4] = v;
            }
        } else {
            for (int i = gt; i < 22 * 40; i += 384) {
                int r = i / 40, c = i % 40;
                A.rawg[r][c] = imload(g, by - 3 + r, bx - 4 + c);
            }
        }
        BAR(10, 384);
        for (int i = gt; i < 20 * 40; i += 384) {
            int r = i / 40, c = i % 40;
            A.vertg[r][c] = (A.rawg[r][c] + 2.0f * A.rawg[r + 1][c] + A.rawg[r + 2][c]) * 0.25f;
        }
        BAR(10, 384);
        for (int i = gt; i < 20 * 40; i += 384) {
            int r = i / 40, c = i % 40;
            unsigned char v = 0;
            if (c < 36) {
                float gb = (A.vertg[r][c + 1] + 2.0f * A.vertg[r][c + 2] + A.vertg[r][c + 3]) * 0.25f;
                int y = by - 2 + r, x = bx - 2 + c;
                bool in = (y >= 0 && y < HH && x >= 0 && x < WW);
                v = in ? quant(gb) : (unsigned char)0;
            }
            A.sgq[r][c] = v;
        }
    }
    __syncthreads();   // sfb / sfq / sgq all ready

    // g template: 5 rows (4 bytes + 1 byte) at origin col tx in sgq
    unsigned int glo[5], ghib[5];
    {
        int k2 = tx & 3, w2 = tx >> 2;
        unsigned int sel = 0x3210u + (unsigned)k2 * 0x1111u;
        #pragma unroll
        for (int ky = 0; ky < 5; ky++) {
            const uint32_t* row = (const uint32_t*)A.sgq[ty + ky];
            uint32_t a = row[w2], b2 = row[w2 + 1];
            glo[ky]  = __byte_perm(a, b2, sel);
            ghib[ky] = (b2 >> (8 * k2)) & 0xFFu;
        }
    }

    if (fgrp) {
        for (int i = ft; i < 26 * 44; i += 640) {   // 26 rows x 4 shifts x 11 words
            int r = i / 44, rem = i % 44;
            int k = rem / 11, ww = rem % 11;
            const uint32_t* W = (const uint32_t*)A.sfq[r];
            uint32_t w0 = W[ww], w1 = W[ww + 1];
            A.sfqs[k][r][ww]  = __byte_perm(w0, w1, 0x3210u + (unsigned)k * 0x1111u);
            A.sfqsH[k][r][ww] = (w1 >> (8 * k)) & 0xFFu;
        }
    } else {
        for (int i = gt; i < 20 * 36; i += 384) {   // gradient of fb
            int r = i / 36, c = i % 36;
            int y = by - 2 + r, x = bx - 2 + c;
            bool in = (y >= 0 && y < HH && x >= 0 && x < WW);
            float dyv = 0.0f, dxv = 0.0f;
            if (in) {
                int yn = min(y + 1, HH - 1) - (by - 5);
                int yp = max(y - 1, 0) - (by - 5);
                int xn = min(x + 1, WW - 1) - (bx - 5);
                int xp = max(x - 1, 0) - (bx - 5);
                dyv = (sfb[yn][c + 3] - sfb[yp][c + 3]) * 0.5f;
                dxv = (sfb[r + 3][xn] - sfb[r + 3][xp]) * 0.5f;
            }
            A.sdy[r][c] = dyv;
            A.sdx[r][c] = dxv;
        }
    }
    __syncthreads();   // sfqs + gradients ready

    // SAD: z0 -> dips 0..2 (z0 also merges+solves LK), z1 -> dips 3..6.
    // Two-wave djp per dip to keep register lives short.
    int best = 0x7fffffff;
    const int dipA = z ? 3 : 0;
    const int dipB = z ? 7 : 3;
    #pragma unroll 1
    for (int dip = dipA; dip < dipB; ++dip) {
        int s = tx + dip;                 // 0..37
        int k = s & 3, wi = s >> 2;
        const uint32_t* bp = &A.sfqs[k][ty][wi];
        const uint32_t* hp = &A.sfqsH[k][ty][wi];

        // wave 1: rows 0..7, djp 0..3
        uint32_t flo[8], fhi[8];
        #pragma unroll
        for (int r = 0; r < 8; r++) {
            flo[r] = bp[r * 12];
            fhi[r] = hp[r * 12];
        }
        #pragma unroll
        for (int djp = 0; djp < 4; djp++) {
            unsigned int sad = 0;
            #pragma unroll
            for (int ky = 0; ky < 5; ky++) {
                sad = __dp4a(__vabsdiffu4(flo[djp + ky], glo[ky]), 0x01010101u, sad);
                sad = __usad(fhi[djp + ky], ghib[ky], sad);
            }
            best = min(best, (int)sad * 4096 + c_rank[djp * 7 + dip]);
        }
        // wave 2: rows 8..10, djp 4..6 (rows 4..7 still live)
        uint32_t flo2[3], fhi2[3];
        #pragma unroll
        for (int r = 0; r < 3; r++) {
            flo2[r] = bp[(8 + r) * 12];
            fhi2[r] = hp[(8 + r) * 12];
        }
        #define ROWL(j) ((j) < 8 ? flo[(j)] : flo2[(j) - 8])
        #define ROWH(j) ((j) < 8 ? fhi[(j)] : fhi2[(j) - 8])
        #pragma unroll
        for (int djp = 4; djp < 7; djp++) {
            unsigned int sad = 0;
            #pragma unroll
            for (int ky = 0; ky < 5; ky++) {
                sad = __dp4a(__vabsdiffu4(ROWL(djp + ky), glo[ky]), 0x01010101u, sad);
                sad = __usad(ROWH(djp + ky), ghib[ky], sad);
            }
            best = min(best, (int)sad * 4096 + c_rank[djp * 7 + dip]);
        }
        #undef ROWL
        #undef ROWH
    }
    sbest[z][ty][tx] = best;
    BAR(qb, 128);                          // pair-local exchange via quad barrier
    best = min(best, sbest[z ^ 1][ty][tx]);

    int bestS = best & 63;
    int bjp = bestS / 7, bip = bestS % 7;

    // Lucas-Kanade ring: z0 -> row 0 (5 pts) + merge + solve; z1 -> rows 1..4 (11 pts)
    float sv, su;   // live across the grid barrier on z0 threads
    {
        float a = 0.f, b = 0.f, d = 0.f, pp = 0.f, q = 0.f;
        #define LKP(ky, kx) { \
            float dx = A.sdx[ty + (ky)][tx + (kx)]; \
            float dy = A.sdy[ty + (ky)][tx + (kx)]; \
            float fv = (float)A.sfq[ty + bjp + (ky)][tx + bip + (kx)] * (1.0f / 255.0f); \
            unsigned int gb = ((kx) < 4) ? ((glo[(ky)] >> (8 * (kx))) & 0xFFu) : ghib[(ky)]; \
            float gv = (float)gb * (1.0f / 255.0f); \
            float zd = gv - fv; \
            a += dx * dx; b += dx * dy; d += dy * dy; \
            pp += zd * dx; q += zd * dy; }
        if (z == 0) {
            LKP(0, 0); LKP(0, 1); LKP(0, 2); LKP(0, 3); LKP(0, 4);
        } else {
            LKP(1, 0); LKP(1, 4);
            LKP(2, 0); LKP(2, 4);
            LKP(3, 0); LKP(3, 4);
            LKP(4, 0); LKP(4, 1); LKP(4, 2); LKP(4, 3); LKP(4, 4);
            sacc[0][ty][tx] = a;  sacc[1][ty][tx] = b;  sacc[2][ty][tx] = d;
            sacc[3][ty][tx] = pp; sacc[4][ty][tx] = q;
        }
        #undef LKP
        BAR(qb, 128);                      // pair-local merge via quad barrier
        if (z == 0) {
            a  += sacc[0][ty][tx]; b += sacc[1][ty][tx]; d += sacc[2][ty][tx];
            pp += sacc[3][ty][tx]; q += sacc[4][ty][tx];
            // avoid FMA contraction: thresholds must match the reference rounding
            float det = __fsub_rn(__fmul_rn(a, d), __fmul_rn(b, b));
            float u   = __fsub_rn(__fmul_rn(d, pp), __fmul_rn(b, q));
            float v   = __fsub_rn(__fmul_rn(a, q), __fmul_rn(b, pp));
            bool bad = (det <= 1e-7f);
            float dd = bad ? 1.0f : det;
            sv = v / dd;   // y component
            su = u / dd;   // x component
            if (bad || fabsf(sv) >= 1.0f) sv = 0.0f;
            if (bad || fabsf(su) >= 1.0f) su = 0.0f;
            sv += (float)(3 - bjp);   // -dj + subpixel
            su += (float)(3 - bip);   // -di + subpixel
            int y = by + ty, x = bx + tx;
            g_flow1[y * WW + x]        = sv;
            g_flow1[NPIX + y * WW + x] = su;
        }
    }

    __syncthreads();   // ALL phase-A smem reads complete -> smem reusable
    if (z == 0) {      // stage own interior directly into phase-B smem
        B.sflow[0][ty + 3][tx + 3] = sv;
        B.sflow[1][ty + 3][tx + 3] = su;
    }

    // ====== GRID BARRIER (128 blocks, all co-resident) ======
    __syncthreads();
    if (tid == 0) {
        unsigned int my;
        asm volatile("atom.add.release.gpu.global.u32 %0, [%1], 1;"
                     : "=r"(my) : "l"(&g_bar) : "memory");
        unsigned int target = my - (my & (NBLK - 1u)) + NBLK;   // end of this round
        unsigned int cur;
        do {
            asm volatile("ld.global.acquire.gpu.u32 %0, [%1];"
                         : "=r"(cur) : "l"(&g_bar) : "memory");
            if (cur >= target) break;
            __nanosleep(64);
        } while (true);
    }
    __syncthreads();

    // ====== PHASE B: median + bilateral ======
    // load ONLY the halo ring (22x38 minus the staged 16x32 interior)
    if (tid < 648) {
        int ch = tid >= 324;
        int i = tid - ch * 324;
        int r, c;
        if (i < 114)      { r = i / 38;              c = i % 38; }
        else if (i < 228) { int j = i - 114; r = 19 + j / 38; c = j % 38; }
        else if (i < 276) { int j = i - 228; r = 3 + j / 3;   c = j % 3; }
        else              { int j = i - 276; r = 3 + j / 3;   c = 35 + j % 3; }
        int y = min(max(by - 3 + r, 0), HH - 1);
        int x = min(max(bx - 3 + c, 0), WW - 1);
        B.sflow[ch][r][c] = g_flow1[ch * NPIX + y * WW + x];
    }
    __syncthreads();

    // median: sflow is loaded at CLAMPED coords, so direct indexing == replicate pad
    for (int i = tid; i < 2 * 720; i += 1024) {      // 20 x 36 per channel
        int ch = i >= 720;
        int rem = i - ch * 720;
        int r = rem / 36, c = rem % 36;
        int y = by - 2 + r, x = bx - 2 + c;
        bool in = (y >= 0 && y < HH && x >= 0 && x < WW);
        float m = 0.0f;
        if (in) {
            const float (*fl)[38] = B.sflow[ch];
            m = median9(fl[r][c],     fl[r][c + 1],     fl[r][c + 2],
                        fl[r + 1][c], fl[r + 1][c + 1], fl[r + 1][c + 2],
                        fl[r + 2][c], fl[r + 2][c + 1], fl[r + 2][c + 2]);
        }
        B.smed[ch][r][c] = m;
        if (ch == 0) B.sguide[r][c] = in ? sfb[r + 3][c + 3] : 0.0f;
    }
    __syncthreads();

    // bilateral: z0 -> 11 taps + merge + divides; z1 -> 14 taps
    {
        const float KVAL = -1.0f / 4.5f;   // -1/(2*1.5^2)
        const float SII  = 200.0f;         //  1/(2*0.05^2)
        float c = B.sguide[ty + 2][tx + 2];
        float wsum = 0.f, s0 = 0.f, s1 = 0.f;

        #define BTAP(dy, dx) { \
            float tn = B.sguide[ty + (dy)][tx + (dx)]; \
            float df = c - tn; \
            float co = 1.0f - fabsf(KVAL - df * df * SII); \
            co = fminf(fmaxf(co, 0.0f), 1.0f); \
            wsum += co; \
            s0 += B.smed[0][ty + (dy)][tx + (dx)] * co; \
            s1 += B.smed[1][ty + (dy)][tx + (dx)] * co; }

        if (z == 0) {
            #pragma unroll
            for (int dy = 0; dy < 2; dy++)
                #pragma unroll
                for (int dx = 0; dx < 5; dx++) BTAP(dy, dx);
            BTAP(2, 0);
        } else {
            BTAP(2, 1); BTAP(2, 2); BTAP(2, 3); BTAP(2, 4);
            #pragma unroll
            for (int dy = 3; dy < 5; dy++)
                #pragma unroll
                for (int dx = 0; dx < 5; dx++) BTAP(dy, dx);
            sacc[0][ty][tx] = wsum;
            sacc[1][ty][tx] = s0;
            sacc[2][ty][tx] = s1;
        }
        #undef BTAP
        BAR(qb, 128);                      // pair-local merge via quad barrier
        if (z == 0) {
            wsum += sacc[0][ty][tx];
            s0   += sacc[1][ty][tx];
            s1   += sacc[2][ty][tx];
            int y = by + ty, x = bx + tx;
            out[y * WW + x]        = s0 / wsum;
            out[NPIX + y * WW + x] = s1 / wsum;
        }
    }
}

// ---------------- launch ----------------
extern "C" void kernel_launch(void* const* d_in, const int* in_sizes, int n_in,
                              void* d_out, int out_size) {
    const float* f = (const float*)d_in[0];
    const float* g = (const float*)d_in[1];
    float* out = (float*)d_out;

    dim3 grd(WW / TW, HH / TH);   // 8 x 16 = 128 blocks, one per SM
    flow_fused<<<grd, 1024>>>(f, g, out);
}

// round 17
// speedup vs baseline: 1.0216x; 1.0043x over previous
#include <cuda_runtime.h>
#include <stdint.h>

#define HH 256
#define WW 256
#define NPIX (HH*WW)
#define TW 32
#define TH 16
#define NBLK 128u

// ---------------- scratch (device globals; no allocations allowed) -------------
__device__ float g_flow1[2*NPIX];   // vector + subpixel (before median)
__device__ unsigned int g_bar;      // grid barrier counter (monotonic across replays)

// packed rank table: (spiral_rank(s) << 6) | s   for s = (dj+3)*7 + (di+3)
__constant__ int c_rank[49] = {
    (42<<6)|0,(43<<6)|1,(44<<6)|2,(45<<6)|3,(46<<6)|4,(47<<6)|5,(48<<6)|6,
    (41<<6)|7,(20<<6)|8,(21<<6)|9,(22<<6)|10,(23<<6)|11,(24<<6)|12,(25<<6)|13,
    (40<<6)|14,(19<<6)|15,(6<<6)|16,(7<<6)|17,(8<<6)|18,(9<<6)|19,(26<<6)|20,
    (39<<6)|21,(18<<6)|22,(5<<6)|23,(0<<6)|24,(1<<6)|25,(10<<6)|26,(27<<6)|27,
    (38<<6)|28,(17<<6)|29,(4<<6)|30,(3<<6)|31,(2<<6)|32,(11<<6)|33,(28<<6)|34,
    (37<<6)|35,(16<<6)|36,(15<<6)|37,(14<<6)|38,(13<<6)|39,(12<<6)|40,(29<<6)|41,
    (36<<6)|42,(35<<6)|43,(34<<6)|44,(33<<6)|45,(32<<6)|46,(31<<6)|47,(30<<6)|48
};

#define BAR(id, cnt) asm volatile("bar.sync %0, %1;" :: "r"(id), "r"(cnt) : "memory")

__device__ __forceinline__ float imload(const float* __restrict__ img, int y, int x) {
    y = min(max(y, 0), HH - 1);
    x = min(max(x, 0), WW - 1);
    return __ldg(&img[y * WW + x]);
}

__device__ __forceinline__ unsigned char quant(float v) {
    float r = rintf(v * 255.0f);          // round half-to-even, matches jnp.round
    r = fminf(fmaxf(r, 0.0f), 255.0f);
    return (unsigned char)r;
}

__device__ __forceinline__ void mnmx(float& a, float& b) {
    float t = fminf(a, b);
    b = fmaxf(a, b);
    a = t;
}
__device__ __forceinline__ float median9(float p0, float p1, float p2,
                                         float p3, float p4, float p5,
                                         float p6, float p7, float p8) {
    mnmx(p1, p2); mnmx(p4, p5); mnmx(p7, p8);
    mnmx(p0, p1); mnmx(p3, p4); mnmx(p6, p7);
    mnmx(p1, p2); mnmx(p4, p5); mnmx(p7, p8);
    mnmx(p0, p3); mnmx(p5, p8); mnmx(p4, p7);
    mnmx(p3, p6); mnmx(p1, p4); mnmx(p2, p5);
    mnmx(p4, p7); mnmx(p4, p2); mnmx(p6, p4);
    mnmx(p4, p2);
    return p4;
}

// phase-overlaid shared memory (sfb + merge arrays persist outside the union)
struct SmemA {
    alignas(16) float rawf[28][48];           // origin (by-6, bx-8)
    alignas(16) unsigned char sfq[26][56];    // origin (by-5, bx-5); cols 0..41 data, 42..47 zero
    alignas(16) uint32_t sfqs[4][26][12];     // shifted copies; plane stride 312 (mod32=24)
    alignas(16) uint32_t sfqsH[4][26][12];    // pre-masked hi bytes (same bank layout)
    alignas(16) float rawg[22][40];           // origin (by-3, bx-4)
    alignas(16) unsigned char sgq[20][40];    // origin (by-2, bx-2); cols 36..39 zero
    float sdx[20][36];                        // origin (by-2, bx-2)
    float sdy[20][36];
};
struct SmemB {
    float sflow[2][22][38];   // flow, halo 3, replicate clamp; origin (by-3, bx-3)
    float smed[2][20][36];    // median flow, halo 2, zero outside; origin (by-2, bx-2)
    float sguide[20][36];     // fb guide, halo 2, zero outside
};

// =====================================================================
// One fused kernel, 128 blocks x 1024 threads (32x16 tile).
// R14 + one-pass binomial (vertical+horizontal fused, bit-identical
// op order) -> one fewer barrier + one fewer smem stage per pipeline.
// =====================================================================
__global__ __launch_bounds__(1024, 1) void flow_fused(const float* __restrict__ f,
                                                      const float* __restrict__ g,
                                                      float* __restrict__ out) {
    __shared__ float sfb[26][42];             // origin (by-5, bx-5); persists to phase B
    __shared__ int   sbest[2][16][32];
    __shared__ float sacc[5][16][32];         // LK partials / bilateral partials
    __shared__ __align__(16) unsigned char smem_raw[
        sizeof(SmemA) > sizeof(SmemB) ? sizeof(SmemA) : sizeof(SmemB)];
    SmemA& A = *reinterpret_cast<SmemA*>(smem_raw);
    SmemB& B = *reinterpret_cast<SmemB*>(smem_raw);

    const int bx = blockIdx.x * TW, by = blockIdx.y * TH;
    const int tid = threadIdx.x;
    const int w   = tid >> 5;
    const int z   = w & 1;            // warp-uniform work-split id
    const int ty  = w >> 1;           // pixel row 0..15
    const int tx  = tid & 31;         // pixel col 0..31
    const int qb  = 1 + (w >> 2);     // warp-quad barrier id (1..8), 128 threads
    const bool fgrp = (w < 20);       // prep pipeline split
    const int ft = tid;               // 0..639 in f-group
    const int gt = tid - 640;         // 0..383 in g-group
    const bool interior = (blockIdx.x > 0 && blockIdx.x < 7 &&
                           blockIdx.y > 0 && blockIdx.y < 15);

    // ====== PHASE A prep: f-pipeline and g-pipeline fully decoupled ======
    if (fgrp) {
        if (interior) {
            if (ft < 28 * 12) {
                int r = ft / 12, w2 = ft % 12;
                float4 v = __ldg((const float4*)(f + (by - 6 + r) * WW + (bx - 8)) + w2);
                *(float4*)&A.rawf[r][w2 * 4] = v;
            }
        } else {
            for (int i = ft; i < 28 * 48; i += 640) {
                int r = i / 48, c = i % 48;
                A.rawf[r][c] = imload(f, by - 6 + r, bx - 8 + c);
            }
        }
        BAR(9, 640);
        // one-pass binomial: vertical sums for cols c+2..c+4, then horizontal.
        // Bit-identical to the two-pass reference order.
        for (int i = ft; i < 26 * 48; i += 640) {
            int r = i / 48, c = i % 48;
            unsigned char v = 0;
            if (c < 42) {
                float v0 = (A.rawf[r][c + 2] + 2.0f * A.rawf[r + 1][c + 2] + A.rawf[r + 2][c + 2]) * 0.25f;
                float v1 = (A.rawf[r][c + 3] + 2.0f * A.rawf[r + 1][c + 3] + A.rawf[r + 2][c + 3]) * 0.25f;
                float v2 = (A.rawf[r][c + 4] + 2.0f * A.rawf[r + 1][c + 4] + A.rawf[r + 2][c + 4]) * 0.25f;
                float fb = (v0 + 2.0f * v1 + v2) * 0.25f;
                sfb[r][c] = fb;
                int y = by - 5 + r, x = bx - 5 + c;
                bool in = (y >= 0 && y < HH && x >= 0 && x < WW);
                v = in ? quant(fb) : (unsigned char)0;
            }
            A.sfq[r][c] = v;
        }
    } else {
        if (interior) {
            if (gt < 22 * 10) {
                int r = gt / 10, w2 = gt % 10;
                float4 v = __ldg((const float4*)(g + (by - 3 + r) * WW + (bx - 4)) + w2);
                *(float4*)&A.rawg[r][w2 * 4] = v;
            }
        } else {
            for (int i = gt; i < 22 * 40; i += 384) {
                int r = i / 40, c = i % 40;
                A.rawg[r][c] = imload(g, by - 3 + r, bx - 4 + c);
            }
        }
        BAR(10, 384);
        for (int i = gt; i < 20 * 40; i += 384) {
            int r = i / 40, c = i % 40;
            unsigned char v = 0;
            if (c < 36) {
                float v0 = (A.rawg[r][c + 1] + 2.0f * A.rawg[r + 1][c + 1] + A.rawg[r + 2][c + 1]) * 0.25f;
                float v1 = (A.rawg[r][c + 2] + 2.0f * A.rawg[r + 1][c + 2] + A.rawg[r + 2][c + 2]) * 0.25f;
                float v2 = (A.rawg[r][c + 3] + 2.0f * A.rawg[r + 1][c + 3] + A.rawg[r + 2][c + 3]) * 0.25f;
                float gb = (v0 + 2.0f * v1 + v2) * 0.25f;
                int y = by - 2 + r, x = bx - 2 + c;
                bool in = (y >= 0 && y < HH && x >= 0 && x < WW);
                v = in ? quant(gb) : (unsigned char)0;
            }
            A.sgq[r][c] = v;
        }
    }
    __syncthreads();   // sfb / sfq / sgq all ready

    // g template: 5 rows (4 bytes + 1 byte) at origin col tx in sgq
    unsigned int glo[5], ghib[5];
    {
        int k2 = tx & 3, w2 = tx >> 2;
        unsigned int sel = 0x3210u + (unsigned)k2 * 0x1111u;
        #pragma unroll
        for (int ky = 0; ky < 5; ky++) {
            const uint32_t* row = (const uint32_t*)A.sgq[ty + ky];
            uint32_t a = row[w2], b2 = row[w2 + 1];
            glo[ky]  = __byte_perm(a, b2, sel);
            ghib[ky] = (b2 >> (8 * k2)) & 0xFFu;
        }
    }

    if (fgrp) {
        for (int i = ft; i < 26 * 44; i += 640) {   // 26 rows x 4 shifts x 11 words
            int r = i / 44, rem = i % 44;
            int k = rem / 11, ww = rem % 11;
            const uint32_t* W = (const uint32_t*)A.sfq[r];
            uint32_t w0 = W[ww], w1 = W[ww + 1];
            A.sfqs[k][r][ww]  = __byte_perm(w0, w1, 0x3210u + (unsigned)k * 0x1111u);
            A.sfqsH[k][r][ww] = (w1 >> (8 * k)) & 0xFFu;
        }
    } else {
        for (int i = gt; i < 20 * 36; i += 384) {   // gradient of fb
            int r = i / 36, c = i % 36;
            int y = by - 2 + r, x = bx - 2 + c;
            bool in = (y >= 0 && y < HH && x >= 0 && x < WW);
            float dyv = 0.0f, dxv = 0.0f;
            if (in) {
                int yn = min(y + 1, HH - 1) - (by - 5);
                int yp = max(y - 1, 0) - (by - 5);
                int xn = min(x + 1, WW - 1) - (bx - 5);
                int xp = max(x - 1, 0) - (bx - 5);
                dyv = (sfb[yn][c + 3] - sfb[yp][c + 3]) * 0.5f;
                dxv = (sfb[r + 3][xn] - sfb[r + 3][xp]) * 0.5f;
            }
            A.sdy[r][c] = dyv;
            A.sdx[r][c] = dxv;
        }
    }
    __syncthreads();   // sfqs + gradients ready

    // SAD: z0 -> dips 0..2 (z0 also merges+solves LK), z1 -> dips 3..6.
    // Two-wave djp per dip to keep register lives short.
    int best = 0x7fffffff;
    const int dipA = z ? 3 : 0;
    const int dipB = z ? 7 : 3;
    #pragma unroll 1
    for (int dip = dipA; dip < dipB; ++dip) {
        int s = tx + dip;                 // 0..37
        int k = s & 3, wi = s >> 2;
        const uint32_t* bp = &A.sfqs[k][ty][wi];
        const uint32_t* hp = &A.sfqsH[k][ty][wi];

        // wave 1: rows 0..7, djp 0..3
        uint32_t flo[8], fhi[8];
        #pragma unroll
        for (int r = 0; r < 8; r++) {
            flo[r] = bp[r * 12];
            fhi[r] = hp[r * 12];
        }
        #pragma unroll
        for (int djp = 0; djp < 4; djp++) {
            unsigned int sad = 0;
            #pragma unroll
            for (int ky = 0; ky < 5; ky++) {
                sad = __dp4a(__vabsdiffu4(flo[djp + ky], glo[ky]), 0x01010101u, sad);
                sad = __usad(fhi[djp + ky], ghib[ky], sad);
            }
            best = min(best, (int)sad * 4096 + c_rank[djp * 7 + dip]);
        }
        // wave 2: rows 8..10, djp 4..6 (rows 4..7 still live)
        uint32_t flo2[3], fhi2[3];
        #pragma unroll
        for (int r = 0; r < 3; r++) {
            flo2[r] = bp[(8 + r) * 12];
            fhi2[r] = hp[(8 + r) * 12];
        }
        #define ROWL(j) ((j) < 8 ? flo[(j)] : flo2[(j) - 8])
        #define ROWH(j) ((j) < 8 ? fhi[(j)] : fhi2[(j) - 8])
        #pragma unroll
        for (int djp = 4; djp < 7; djp++) {
            unsigned int sad = 0;
            #pragma unroll
            for (int ky = 0; ky < 5; ky++) {
                sad = __dp4a(__vabsdiffu4(ROWL(djp + ky), glo[ky]), 0x01010101u, sad);
                sad = __usad(ROWH(djp + ky), ghib[ky], sad);
            }
            best = min(best, (int)sad * 4096 + c_rank[djp * 7 + dip]);
        }
        #undef ROWL
        #undef ROWH
    }
    sbest[z][ty][tx] = best;
    BAR(qb, 128);                          // pair-local exchange via quad barrier
    best = min(best, sbest[z ^ 1][ty][tx]);

    int bestS = best & 63;
    int bjp = bestS / 7, bip = bestS % 7;

    // Lucas-Kanade ring: z0 -> row 0 (5 pts) + merge + solve; z1 -> rows 1..4 (11 pts)
    float sv, su;   // live across the grid barrier on z0 threads
    {
        float a = 0.f, b = 0.f, d = 0.f, pp = 0.f, q = 0.f;
        #define LKP(ky, kx) { \
            float dx = A.sdx[ty + (ky)][tx + (kx)]; \
            float dy = A.sdy[ty + (ky)][tx + (kx)]; \
            float fv = (float)A.sfq[ty + bjp + (ky)][tx + bip + (kx)] * (1.0f / 255.0f); \
            unsigned int gb = ((kx) < 4) ? ((glo[(ky)] >> (8 * (kx))) & 0xFFu) : ghib[(ky)]; \
            float gv = (float)gb * (1.0f / 255.0f); \
            float zd = gv - fv; \
            a += dx * dx; b += dx * dy; d += dy * dy; \
            pp += zd * dx; q += zd * dy; }
        if (z == 0) {
            LKP(0, 0); LKP(0, 1); LKP(0, 2); LKP(0, 3); LKP(0, 4);
        } else {
            LKP(1, 0); LKP(1, 4);
            LKP(2, 0); LKP(2, 4);
            LKP(3, 0); LKP(3, 4);
            LKP(4, 0); LKP(4, 1); LKP(4, 2); LKP(4, 3); LKP(4, 4);
            sacc[0][ty][tx] = a;  sacc[1][ty][tx] = b;  sacc[2][ty][tx] = d;
            sacc[3][ty][tx] = pp; sacc[4][ty][tx] = q;
        }
        #undef LKP
        BAR(qb, 128);                      // pair-local merge via quad barrier
        if (z == 0) {
            a  += sacc[0][ty][tx]; b += sacc[1][ty][tx]; d += sacc[2][ty][tx];
            pp += sacc[3][ty][tx]; q += sacc[4][ty][tx];
            // avoid FMA contraction: thresholds must match the reference rounding
            float det = __fsub_rn(__fmul_rn(a, d), __fmul_rn(b, b));
            float u   = __fsub_rn(__fmul_rn(d, pp), __fmul_rn(b, q));
            float v   = __fsub_rn(__fmul_rn(a, q), __fmul_rn(b, pp));
            bool bad = (det <= 1e-7f);
            float dd = bad ? 1.0f : det;
            sv = v / dd;   // y component
            su = u / dd;   // x component
            if (bad || fabsf(sv) >= 1.0f) sv = 0.0f;
            if (bad || fabsf(su) >= 1.0f) su = 0.0f;
            sv += (float)(3 - bjp);   // -dj + subpixel
            su += (float)(3 - bip);   // -di + subpixel
            int y = by + ty, x = bx + tx;
            g_flow1[y * WW + x]        = sv;
            g_flow1[NPIX + y * WW + x] = su;
        }
    }

    __syncthreads();   // ALL phase-A smem reads complete -> smem reusable
    if (z == 0) {      // stage own interior directly into phase-B smem
        B.sflow[0][ty + 3][tx + 3] = sv;
        B.sflow[1][ty + 3][tx + 3] = su;
    }

    // ====== GRID BARRIER (128 blocks, all co-resident) ======
    __syncthreads();
    if (tid == 0) {
        unsigned int my;
        asm volatile("atom.add.release.gpu.global.u32 %0, [%1], 1;"
                     : "=r"(my) : "l"(&g_bar) : "memory");
        unsigned int target = my - (my & (NBLK - 1u)) + NBLK;   // end of this round
        unsigned int cur;
        do {
            asm volatile("ld.global.acquire.gpu.u32 %0, [%1];"
                         : "=r"(cur) : "l"(&g_bar) : "memory");
            if (cur >= target) break;
            __nanosleep(64);
        } while (true);
    }
    __syncthreads();

    // ====== PHASE B: median + bilateral ======
    // load ONLY the halo ring (22x38 minus the staged 16x32 interior)
    if (tid < 648) {
        int ch = tid >= 324;
        int i = tid - ch * 324;
        int r, c;
        if (i < 114)      { r = i / 38;              c = i % 38; }
        else if (i < 228) { int j = i - 114; r = 19 + j / 38; c = j % 38; }
        else if (i < 276) { int j = i - 228; r = 3 + j / 3;   c = j % 3; }
        else              { int j = i - 276; r = 3 + j / 3;   c = 35 + j % 3; }
        int y = min(max(by - 3 + r, 0), HH - 1);
        int x = min(max(bx - 3 + c, 0), WW - 1);
        B.sflow[ch][r][c] = g_flow1[ch * NPIX + y * WW + x];
    }
    __syncthreads();

    // median: sflow is loaded at CLAMPED coords, so direct indexing == replicate pad
    for (int i = tid; i < 2 * 720; i += 1024) {      // 20 x 36 per channel
        int ch = i >= 720;
        int rem = i - ch * 720;
        int r = rem / 36, c = rem % 36;
        int y = by - 2 + r, x = bx - 2 + c;
        bool in = (y >= 0 && y < HH && x >= 0 && x < WW);
        float m = 0.0f;
        if (in) {
            const float (*fl)[38] = B.sflow[ch];
            m = median9(fl[r][c],     fl[r][c + 1],     fl[r][c + 2],
                        fl[r + 1][c], fl[r + 1][c + 1], fl[r + 1][c + 2],
                        fl[r + 2][c], fl[r + 2][c + 1], fl[r + 2][c + 2]);
        }
        B.smed[ch][r][c] = m;
        if (ch == 0) B.sguide[r][c] = in ? sfb[r + 3][c + 3] : 0.0f;
    }
    __syncthreads();

    // bilateral: z0 -> 11 taps + merge + divides; z1 -> 14 taps
    {
        const float KVAL = -1.0f / 4.5f;   // -1/(2*1.5^2)
        const float SII  = 200.0f;         //  1/(2*0.05^2)
        float c = B.sguide[ty + 2][tx + 2];
        float wsum = 0.f, s0 = 0.f, s1 = 0.f;

        #define BTAP(dy, dx) { \
            float tn = B.sguide[ty + (dy)][tx + (dx)]; \
            float df = c - tn; \
            float co = 1.0f - fabsf(KVAL - df * df * SII); \
            co = fminf(fmaxf(co, 0.0f), 1.0f); \
            wsum += co; \
            s0 += B.smed[0][ty + (dy)][tx + (dx)] * co; \
            s1 += B.smed[1][ty + (dy)][tx + (dx)] * co; }

        if (z == 0) {
            #pragma unroll
            for (int dy = 0; dy < 2; dy++)
                #pragma unroll
                for (int dx = 0; dx < 5; dx++) BTAP(dy, dx);
            BTAP(2, 0);
        } else {
            BTAP(2, 1); BTAP(2, 2); BTAP(2, 3); BTAP(2, 4);
            #pragma unroll
            for (int dy = 3; dy < 5; dy++)
                #pragma unroll
                for (int dx = 0; dx < 5; dx++) BTAP(dy, dx);
            sacc[0][ty][tx] = wsum;
            sacc[1][ty][tx] = s0;
            sacc[2][ty][tx] = s1;
        }
        #undef BTAP
        BAR(qb, 128);                      // pair-local merge via quad barrier
        if (z == 0) {
            wsum += sacc[0][ty][tx];
            s0   += sacc[1][ty][tx];
            s1   += sacc[2][ty][tx];
            int y = by + ty, x = bx + tx;
            out[y * WW + x]        = s0 / wsum;
            out[NPIX + y * WW + x] = s1 / wsum;
        }
    }
}

// ---------------- launch ----------------
extern "C" void kernel_launch(void* const* d_in, const int* in_sizes, int n_in,
                              void* d_out, int out_size) {
    const float* f = (const float*)d_in[0];
    const float* g = (const float*)d_in[1];
    float* out = (float*)d_out;

    dim3 grd(WW / TW, HH / TH);   // 8 x 16 = 128 blocks, one per SM
    flow_fused<<<grd, 1024>>>(f, g, out);
}